// round 6
// baseline (speedup 1.0000x reference)
#include <cuda_runtime.h>
#include <cuda_fp16.h>
#include <cstdint>

// ======================= problem sizes =======================
#define D_IN   4096
#define D_OUT  4096
#define M_TOT  8192
#define MT     128             // CTA M tile
#define NT     256             // CTA N tile
#define KC     64              // K chunk: 64 fp16 = 128B rows (SW128)
#define STAGES 4
#define KITERS (D_IN / KC)     // 64
#define NTHREADS 512

// ======================= scratch =======================
static __device__ __half g_W[(size_t)D_OUT * D_IN];   // 32 MB
static __device__ __half g_X[(size_t)M_TOT * D_IN];   // 64 MB
static __device__ float  g_bias[D_OUT];

__constant__ float NF4_CB[16] = {
  -1.0f, -0.6961928009986877f, -0.5250730514526367f, -0.39491748809814453f,
  -0.28444138169288635f, -0.18477343022823334f, -0.09105003625154495f, 0.0f,
  0.07958029955625534f, 0.16093020141124725f, 0.24611230194568634f,
  0.33791524171829224f, 0.44070982933044434f, 0.5626170039176941f,
  0.6848514676094055f, 1.0f };

// ======================= helpers =======================
__device__ __forceinline__ uint32_t smem_u32(const void* p){
  uint32_t a;
  asm("{ .reg .u64 t; cvta.to.shared.u64 t, %1; cvt.u32.u64 %0, t; }" : "=r"(a) : "l"(p));
  return a;
}
__device__ __forceinline__ uint32_t pack_h2(float a, float b){
  __half2 h = __floats2half2_rn(a, b);
  return *reinterpret_cast<uint32_t*>(&h);
}
__device__ __forceinline__ void cp16(uint32_t s, const void* g){
  asm volatile("cp.async.cg.shared.global [%0], [%1], 16;" :: "r"(s), "l"(g) : "memory");
}
__device__ __forceinline__ void cp_commit(){
  asm volatile("cp.async.commit_group;" ::: "memory");
}
template<int N> __device__ __forceinline__ void cp_wait(){
  asm volatile("cp.async.wait_group %0;" :: "n"(N) : "memory");
}
__device__ __forceinline__ void ldsm_x4(uint32_t* r, uint32_t addr){
  asm volatile("ldmatrix.sync.aligned.m8n8.x4.shared.b16 {%0,%1,%2,%3}, [%4];"
               : "=r"(r[0]), "=r"(r[1]), "=r"(r[2]), "=r"(r[3]) : "r"(addr));
}
__device__ __forceinline__ void mma16816(float* c, const uint32_t* a, const uint32_t* b){
  asm volatile("mma.sync.aligned.m16n8k16.row.col.f32.f16.f16.f32 "
               "{%0,%1,%2,%3}, {%4,%5,%6,%7}, {%8,%9}, {%0,%1,%2,%3};"
               : "+f"(c[0]), "+f"(c[1]), "+f"(c[2]), "+f"(c[3])
               : "r"(a[0]), "r"(a[1]), "r"(a[2]), "r"(a[3]), "r"(b[0]), "r"(b[1]));
}

// ======================= dequant / convert kernels =======================
__global__ void k_dequant_w(const int* __restrict__ codes, const float* __restrict__ absmax){
  size_t i = ((size_t)blockIdx.x * blockDim.x + threadIdx.x) * 8;
  float am = absmax[i >> 6];
  int4 c0 = *reinterpret_cast<const int4*>(codes + i);
  int4 c1 = *reinterpret_cast<const int4*>(codes + i + 4);
  uint4 o;
  o.x = pack_h2(NF4_CB[c0.x] * am, NF4_CB[c0.y] * am);
  o.y = pack_h2(NF4_CB[c0.z] * am, NF4_CB[c0.w] * am);
  o.z = pack_h2(NF4_CB[c1.x] * am, NF4_CB[c1.y] * am);
  o.w = pack_h2(NF4_CB[c1.z] * am, NF4_CB[c1.w] * am);
  *reinterpret_cast<uint4*>(g_W + i) = o;
}

__global__ void k_conv_x(const float* __restrict__ x){
  size_t i = ((size_t)blockIdx.x * blockDim.x + threadIdx.x) * 8;
  float4 a = *reinterpret_cast<const float4*>(x + i);
  float4 b = *reinterpret_cast<const float4*>(x + i + 4);
  uint4 o;
  o.x = pack_h2(a.x, a.y);  o.y = pack_h2(a.z, a.w);
  o.z = pack_h2(b.x, b.y);  o.w = pack_h2(b.z, b.w);
  *reinterpret_cast<uint4*>(g_X + i) = o;
}

__global__ void k_dequant_b(const int* __restrict__ codes, const float* __restrict__ absmax){
  int i = blockIdx.x * blockDim.x + threadIdx.x;
  if (i < D_OUT) g_bias[i] = NF4_CB[codes[i]] * absmax[i >> 6];
}

// ======================= GEMM =======================
#define A_BYTES     (MT * KC * 2)            // 16 KB
#define STAGE_BYTES ((MT + NT) * KC * 2)     // 48 KB
#define SMEM_BYTES  (STAGES * STAGE_BYTES)   // 192 KB -> 1 CTA/SM

// load one K-chunk (chunk index kt) into stage s. 512 threads, 6 x 16B each.
__device__ __forceinline__ void load_stage(uint32_t sb, int s, int kt,
                                           const __half* gA, const __half* gB){
  uint32_t base = sb + (uint32_t)s * STAGE_BYTES;
  int t = threadIdx.x;
  #pragma unroll
  for (int i = 0; i < 2; ++i){                 // A: 128 rows x 8 chunks = 1024
    int ci  = t + i * NTHREADS;
    int row = ci >> 3, c = ci & 7;
    uint32_t sw = (uint32_t)((c ^ (row & 7)) << 4);
    cp16(base + (uint32_t)(row * 128) + sw,
         gA + (size_t)row * D_IN + kt * KC + c * 8);
  }
  #pragma unroll
  for (int i = 0; i < 4; ++i){                 // B: 256 rows x 8 chunks = 2048
    int ci  = t + i * NTHREADS;
    int row = ci >> 3, c = ci & 7;
    uint32_t sw = (uint32_t)((c ^ (row & 7)) << 4);
    cp16(base + A_BYTES + (uint32_t)(row * 128) + sw,
         gB + (size_t)row * D_IN + kt * KC + c * 8);
  }
}

__global__ void __launch_bounds__(NTHREADS, 1)
k_gemm(float* __restrict__ out){
  extern __shared__ char smem[];
  uint32_t sb = smem_u32(smem);
  const int tid = threadIdx.x;
  const int wid = tid >> 5;
  const int l   = tid & 31;

  const int m0g = blockIdx.y * MT;
  const int n0g = blockIdx.x * NT;
  const __half* gA = g_X + (size_t)m0g * D_IN;
  const __half* gB = g_W + (size_t)n0g * D_IN;

  // warp layout: 4 (m) x 4 (n); warp tile 32(m) x 64(n)
  const int wm = (wid & 3) * 32;
  const int wn = (wid >> 2) * 64;

  // ldmatrix lane addressing
  const int rA   = wm + (l & 15);
  const int hiA  = l >> 4;
  const int r7A  = rA & 7;
  const int rB   = wn + ((l & 16) >> 1) + (l & 7);
  const int hiB  = (l >> 3) & 1;
  const int r7B  = rB & 7;

  float acc[2][8][4];
  #pragma unroll
  for (int f = 0; f < 2; ++f)
    #pragma unroll
    for (int j = 0; j < 8; ++j)
      #pragma unroll
      for (int q = 0; q < 4; ++q) acc[f][j][q] = 0.f;

  // prologue: stages 0..STAGES-2
  #pragma unroll
  for (int s = 0; s < STAGES - 1; ++s){
    load_stage(sb, s, s, gA, gB);
    cp_commit();
  }

  for (int kt = 0; kt < KITERS; ++kt){
    cp_wait<STAGES - 2>();
    __syncthreads();   // single barrier: orders compute(kt-1) before the
                       // overwrite of its buffer, and publishes stage kt

    int kn = kt + STAGES - 1;
    if (kn < KITERS) load_stage(sb, kn % STAGES, kn, gA, gB);
    cp_commit();

    uint32_t As = sb + (uint32_t)((kt % STAGES) * STAGE_BYTES);
    uint32_t Bs = As + A_BYTES;
    uint32_t baseA = As + (uint32_t)(rA * 128);
    uint32_t baseB = Bs + (uint32_t)(rB * 128);

    #pragma unroll
    for (int ks = 0; ks < 4; ++ks){
      uint32_t csA = (uint32_t)(((2 * ks + hiA) ^ r7A) << 4);
      uint32_t csB = (uint32_t)(((2 * ks + hiB) ^ r7B) << 4);
      uint32_t a[2][4];
      #pragma unroll
      for (int f = 0; f < 2; ++f)
        ldsm_x4(a[f], baseA + (uint32_t)(f * 2048) + csA);
      #pragma unroll
      for (int nf = 0; nf < 4; ++nf){
        uint32_t b[4];
        ldsm_x4(b, baseB + (uint32_t)(nf * 2048) + csB);
        #pragma unroll
        for (int f = 0; f < 2; ++f){
          mma16816(acc[f][2 * nf + 0], a[f], b + 0);
          mma16816(acc[f][2 * nf + 1], a[f], b + 2);
        }
      }
    }
  }

  // ---------------- epilogue ----------------
  const int gid = l >> 2, tig = l & 3;
  const int colbase = n0g + wn + 2 * tig;
  #pragma unroll
  for (int f = 0; f < 2; ++f){
    int row0 = m0g + wm + 16 * f + gid;
    float* o0 = out + (size_t)row0 * D_OUT;
    float* o1 = o0 + (size_t)8 * D_OUT;
    #pragma unroll
    for (int j = 0; j < 8; ++j){
      int cg = colbase + 8 * j;
      float b0 = g_bias[cg], b1 = g_bias[cg + 1];
      float2 v0 = { acc[f][j][0] + b0, acc[f][j][1] + b1 };
      float2 v1 = { acc[f][j][2] + b0, acc[f][j][3] + b1 };
      *reinterpret_cast<float2*>(o0 + cg) = v0;
      *reinterpret_cast<float2*>(o1 + cg) = v1;
    }
  }
}

// ======================= launch =======================
extern "C" void kernel_launch(void* const* d_in, const int* in_sizes, int n_in,
                              void* d_out, int out_size){
  const float* x  = (const float*)d_in[0];
  const int*   wc = (const int*)  d_in[1];
  const float* wa = (const float*)d_in[2];
  const int*   bc = (const int*)  d_in[3];
  const float* ba = (const float*)d_in[4];
  float* out = (float*)d_out;

  cudaFuncSetAttribute(k_gemm, cudaFuncAttributeMaxDynamicSharedMemorySize, SMEM_BYTES);

  k_dequant_w<<<(int)(((size_t)D_OUT * D_IN / 8) / 256), 256>>>(wc, wa);
  k_conv_x   <<<(int)(((size_t)M_TOT * D_IN / 8) / 256), 256>>>(x);
  k_dequant_b<<<(D_OUT + 255) / 256, 256>>>(bc, ba);

  dim3 grid(D_OUT / NT, M_TOT / MT);   // (16, 64)
  k_gemm<<<grid, NTHREADS, SMEM_BYTES>>>(out);
}

// round 7
// speedup vs baseline: 1.0468x; 1.0468x over previous
#include <cuda_runtime.h>
#include <cuda_fp16.h>
#include <cstdint>

// ======================= problem sizes =======================
#define D_IN   4096
#define D_OUT  4096
#define M_TOT  8192
#define MT     128             // CTA M tile
#define NT     256             // CTA N tile
#define KC     64              // K chunk: 64 fp16 = 128B rows (SW128)
#define STAGES 4
#define KITERS (D_IN / KC)     // 64
#define NTHREADS 256           // 8 warps, warp tile 64x64

// ======================= scratch =======================
static __device__ __half g_W[(size_t)D_OUT * D_IN];   // 32 MB
static __device__ __half g_X[(size_t)M_TOT * D_IN];   // 64 MB
static __device__ float  g_bias[D_OUT];

__constant__ float NF4_CB[16] = {
  -1.0f, -0.6961928009986877f, -0.5250730514526367f, -0.39491748809814453f,
  -0.28444138169288635f, -0.18477343022823334f, -0.09105003625154495f, 0.0f,
  0.07958029955625534f, 0.16093020141124725f, 0.24611230194568634f,
  0.33791524171829224f, 0.44070982933044434f, 0.5626170039176941f,
  0.6848514676094055f, 1.0f };

// ======================= helpers =======================
__device__ __forceinline__ uint32_t smem_u32(const void* p){
  uint32_t a;
  asm("{ .reg .u64 t; cvta.to.shared.u64 t, %1; cvt.u32.u64 %0, t; }" : "=r"(a) : "l"(p));
  return a;
}
__device__ __forceinline__ uint32_t pack_h2(float a, float b){
  __half2 h = __floats2half2_rn(a, b);
  return *reinterpret_cast<uint32_t*>(&h);
}
__device__ __forceinline__ void cp16(uint32_t s, const void* g){
  asm volatile("cp.async.cg.shared.global [%0], [%1], 16;" :: "r"(s), "l"(g) : "memory");
}
__device__ __forceinline__ void cp_commit(){
  asm volatile("cp.async.commit_group;" ::: "memory");
}
template<int N> __device__ __forceinline__ void cp_wait(){
  asm volatile("cp.async.wait_group %0;" :: "n"(N) : "memory");
}
__device__ __forceinline__ void ldsm_x4(uint32_t* r, uint32_t addr){
  asm volatile("ldmatrix.sync.aligned.m8n8.x4.shared.b16 {%0,%1,%2,%3}, [%4];"
               : "=r"(r[0]), "=r"(r[1]), "=r"(r[2]), "=r"(r[3]) : "r"(addr));
}
__device__ __forceinline__ void mma16816(float* c, const uint32_t* a, const uint32_t* b){
  asm volatile("mma.sync.aligned.m16n8k16.row.col.f32.f16.f16.f32 "
               "{%0,%1,%2,%3}, {%4,%5,%6,%7}, {%8,%9}, {%0,%1,%2,%3};"
               : "+f"(c[0]), "+f"(c[1]), "+f"(c[2]), "+f"(c[3])
               : "r"(a[0]), "r"(a[1]), "r"(a[2]), "r"(a[3]), "r"(b[0]), "r"(b[1]));
}

// ======================= dequant / convert kernels =======================
// NF4 LUT lives in shared memory: divergent per-lane indices into __constant__
// serialize on the constant port (up to 16 replays); LDS broadcasts/banks fine.
__global__ void k_dequant_w(const int* __restrict__ codes, const float* __restrict__ absmax){
  __shared__ float lut[16];
  if (threadIdx.x < 16) lut[threadIdx.x] = NF4_CB[threadIdx.x];
  __syncthreads();
  size_t i = ((size_t)blockIdx.x * blockDim.x + threadIdx.x) * 8;
  float am = absmax[i >> 6];
  int4 c0 = *reinterpret_cast<const int4*>(codes + i);
  int4 c1 = *reinterpret_cast<const int4*>(codes + i + 4);
  uint4 o;
  o.x = pack_h2(lut[c0.x] * am, lut[c0.y] * am);
  o.y = pack_h2(lut[c0.z] * am, lut[c0.w] * am);
  o.z = pack_h2(lut[c1.x] * am, lut[c1.y] * am);
  o.w = pack_h2(lut[c1.z] * am, lut[c1.w] * am);
  *reinterpret_cast<uint4*>(g_W + i) = o;
}

__global__ void k_conv_x(const float* __restrict__ x){
  size_t i = ((size_t)blockIdx.x * blockDim.x + threadIdx.x) * 8;
  float4 a = *reinterpret_cast<const float4*>(x + i);
  float4 b = *reinterpret_cast<const float4*>(x + i + 4);
  uint4 o;
  o.x = pack_h2(a.x, a.y);  o.y = pack_h2(a.z, a.w);
  o.z = pack_h2(b.x, b.y);  o.w = pack_h2(b.z, b.w);
  *reinterpret_cast<uint4*>(g_X + i) = o;
}

__global__ void k_dequant_b(const int* __restrict__ codes, const float* __restrict__ absmax){
  __shared__ float lut[16];
  if (threadIdx.x < 16) lut[threadIdx.x] = NF4_CB[threadIdx.x];
  __syncthreads();
  int i = blockIdx.x * blockDim.x + threadIdx.x;
  if (i < D_OUT) g_bias[i] = lut[codes[i]] * absmax[i >> 6];
}

// ======================= GEMM =======================
#define A_BYTES     (MT * KC * 2)            // 16 KB
#define STAGE_BYTES ((MT + NT) * KC * 2)     // 48 KB
#define SMEM_BYTES  (STAGES * STAGE_BYTES)   // 192 KB -> 1 CTA/SM

// load one K-chunk (chunk index kt) into stage s. 256 threads, 12 x 16B each.
__device__ __forceinline__ void load_stage(uint32_t sb, int s, int kt,
                                           const __half* gA, const __half* gB){
  uint32_t base = sb + (uint32_t)s * STAGE_BYTES;
  int t = threadIdx.x;
  #pragma unroll
  for (int i = 0; i < 4; ++i){                 // A: 128 rows x 8 chunks = 1024
    int ci  = t + i * NTHREADS;
    int row = ci >> 3, c = ci & 7;
    uint32_t sw = (uint32_t)((c ^ (row & 7)) << 4);
    cp16(base + (uint32_t)(row * 128) + sw,
         gA + (size_t)row * D_IN + kt * KC + c * 8);
  }
  #pragma unroll
  for (int i = 0; i < 8; ++i){                 // B: 256 rows x 8 chunks = 2048
    int ci  = t + i * NTHREADS;
    int row = ci >> 3, c = ci & 7;
    uint32_t sw = (uint32_t)((c ^ (row & 7)) << 4);
    cp16(base + A_BYTES + (uint32_t)(row * 128) + sw,
         gB + (size_t)row * D_IN + kt * KC + c * 8);
  }
}

__global__ void __launch_bounds__(NTHREADS, 1)
k_gemm(float* __restrict__ out){
  extern __shared__ char smem[];
  uint32_t sb = smem_u32(smem);
  const int tid = threadIdx.x;
  const int wid = tid >> 5;
  const int l   = tid & 31;

  const int m0g = blockIdx.y * MT;
  const int n0g = blockIdx.x * NT;
  const __half* gA = g_X + (size_t)m0g * D_IN;
  const __half* gB = g_W + (size_t)n0g * D_IN;

  // warp layout: 2 (m) x 4 (n); warp tile 64(m) x 64(n)
  const int wm = (wid & 1) * 64;
  const int wn = (wid >> 1) * 64;

  // ldmatrix lane addressing
  const int rA   = wm + (l & 15);          // + 16*f below
  const int hiA  = l >> 4;
  const int r7A  = rA & 7;
  const int rB   = wn + ((l & 16) >> 1) + (l & 7);   // + 16*nf below
  const int hiB  = (l >> 3) & 1;
  const int r7B  = rB & 7;

  float acc[4][8][4];
  #pragma unroll
  for (int f = 0; f < 4; ++f)
    #pragma unroll
    for (int j = 0; j < 8; ++j)
      #pragma unroll
      for (int q = 0; q < 4; ++q) acc[f][j][q] = 0.f;

  // prologue: stages 0..STAGES-2
  #pragma unroll
  for (int s = 0; s < STAGES - 1; ++s){
    load_stage(sb, s, s, gA, gB);
    cp_commit();
  }

  for (int kt = 0; kt < KITERS; ++kt){
    cp_wait<STAGES - 2>();
    __syncthreads();   // single barrier: orders compute(kt-1) before the
                       // overwrite of its buffer, and publishes stage kt

    int kn = kt + STAGES - 1;
    if (kn < KITERS) load_stage(sb, kn % STAGES, kn, gA, gB);
    cp_commit();

    uint32_t As = sb + (uint32_t)((kt % STAGES) * STAGE_BYTES);
    uint32_t Bs = As + A_BYTES;
    uint32_t baseA = As + (uint32_t)(rA * 128);
    uint32_t baseB = Bs + (uint32_t)(rB * 128);

    #pragma unroll
    for (int ks = 0; ks < 4; ++ks){
      uint32_t csA = (uint32_t)(((2 * ks + hiA) ^ r7A) << 4);
      uint32_t csB = (uint32_t)(((2 * ks + hiB) ^ r7B) << 4);
      uint32_t a[4][4];
      #pragma unroll
      for (int f = 0; f < 4; ++f)                 // A: 64 m-rows = 4 frags
        ldsm_x4(a[f], baseA + (uint32_t)(f * 2048) + csA);
      #pragma unroll
      for (int nf = 0; nf < 4; ++nf){             // B: 64 n-cols = 4 ldsm
        uint32_t b[4];
        ldsm_x4(b, baseB + (uint32_t)(nf * 2048) + csB);
        #pragma unroll
        for (int f = 0; f < 4; ++f){
          mma16816(acc[f][2 * nf + 0], a[f], b + 0);
          mma16816(acc[f][2 * nf + 1], a[f], b + 2);
        }
      }
    }
  }

  // ---------------- epilogue ----------------
  const int gid = l >> 2, tig = l & 3;
  const int colbase = n0g + wn + 2 * tig;
  #pragma unroll
  for (int f = 0; f < 4; ++f){
    int row0 = m0g + wm + 16 * f + gid;
    float* o0 = out + (size_t)row0 * D_OUT;
    float* o1 = o0 + (size_t)8 * D_OUT;
    #pragma unroll
    for (int j = 0; j < 8; ++j){
      int cg = colbase + 8 * j;
      float b0 = g_bias[cg], b1 = g_bias[cg + 1];
      float2 v0 = { acc[f][j][0] + b0, acc[f][j][1] + b1 };
      float2 v1 = { acc[f][j][2] + b0, acc[f][j][3] + b1 };
      *reinterpret_cast<float2*>(o0 + cg) = v0;
      *reinterpret_cast<float2*>(o1 + cg) = v1;
    }
  }
}

// ======================= launch =======================
extern "C" void kernel_launch(void* const* d_in, const int* in_sizes, int n_in,
                              void* d_out, int out_size){
  const float* x  = (const float*)d_in[0];
  const int*   wc = (const int*)  d_in[1];
  const float* wa = (const float*)d_in[2];
  const int*   bc = (const int*)  d_in[3];
  const float* ba = (const float*)d_in[4];
  float* out = (float*)d_out;

  cudaFuncSetAttribute(k_gemm, cudaFuncAttributeMaxDynamicSharedMemorySize, SMEM_BYTES);

  k_dequant_w<<<(int)(((size_t)D_OUT * D_IN / 8) / 256), 256>>>(wc, wa);
  k_conv_x   <<<(int)(((size_t)M_TOT * D_IN / 8) / 256), 256>>>(x);
  k_dequant_b<<<(D_OUT + 255) / 256, 256>>>(bc, ba);

  dim3 grid(D_OUT / NT, M_TOT / MT);   // (16, 64)
  k_gemm<<<grid, NTHREADS, SMEM_BYTES>>>(out);
}

// round 8
// speedup vs baseline: 1.0909x; 1.0422x over previous
#include <cuda_runtime.h>
#include <cuda_fp16.h>
#include <cstdint>

// ======================= problem sizes =======================
#define D_IN   4096
#define D_OUT  4096
#define M_TOT  8192
#define MT     128             // CTA M tile
#define NT     256             // CTA N tile
#define KC     64              // K chunk: 64 fp16 = 128B rows (SW128)
#define KITERS (D_IN / KC)     // 64 chunks -> 32 pairs
#define NTHREADS 256           // 8 warps, warp tile 64x64

// ======================= scratch =======================
static __device__ __half g_W[(size_t)D_OUT * D_IN];   // 32 MB
static __device__ __half g_X[(size_t)M_TOT * D_IN];   // 64 MB
static __device__ float  g_bias[D_OUT];

__constant__ float NF4_CB[16] = {
  -1.0f, -0.6961928009986877f, -0.5250730514526367f, -0.39491748809814453f,
  -0.28444138169288635f, -0.18477343022823334f, -0.09105003625154495f, 0.0f,
  0.07958029955625534f, 0.16093020141124725f, 0.24611230194568634f,
  0.33791524171829224f, 0.44070982933044434f, 0.5626170039176941f,
  0.6848514676094055f, 1.0f };

// ======================= helpers =======================
__device__ __forceinline__ uint32_t smem_u32(const void* p){
  uint32_t a;
  asm("{ .reg .u64 t; cvta.to.shared.u64 t, %1; cvt.u32.u64 %0, t; }" : "=r"(a) : "l"(p));
  return a;
}
__device__ __forceinline__ uint32_t pack_h2(float a, float b){
  __half2 h = __floats2half2_rn(a, b);
  return *reinterpret_cast<uint32_t*>(&h);
}
__device__ __forceinline__ void cp16(uint32_t s, const void* g){
  asm volatile("cp.async.cg.shared.global [%0], [%1], 16;" :: "r"(s), "l"(g) : "memory");
}
__device__ __forceinline__ void cp_commit(){
  asm volatile("cp.async.commit_group;" ::: "memory");
}
template<int N> __device__ __forceinline__ void cp_wait(){
  asm volatile("cp.async.wait_group %0;" :: "n"(N) : "memory");
}
__device__ __forceinline__ void ldsm_x4(uint32_t* r, uint32_t addr){
  asm volatile("ldmatrix.sync.aligned.m8n8.x4.shared.b16 {%0,%1,%2,%3}, [%4];"
               : "=r"(r[0]), "=r"(r[1]), "=r"(r[2]), "=r"(r[3]) : "r"(addr));
}
__device__ __forceinline__ void mma16816(float* c, const uint32_t* a, const uint32_t* b){
  asm volatile("mma.sync.aligned.m16n8k16.row.col.f32.f16.f16.f32 "
               "{%0,%1,%2,%3}, {%4,%5,%6,%7}, {%8,%9}, {%0,%1,%2,%3};"
               : "+f"(c[0]), "+f"(c[1]), "+f"(c[2]), "+f"(c[3])
               : "r"(a[0]), "r"(a[1]), "r"(a[2]), "r"(a[3]), "r"(b[0]), "r"(b[1]));
}

// ======================= dequant / convert kernels =======================
__global__ void k_dequant_w(const int* __restrict__ codes, const float* __restrict__ absmax){
  __shared__ float lut[16];
  if (threadIdx.x < 16) lut[threadIdx.x] = NF4_CB[threadIdx.x];
  __syncthreads();
  size_t i = ((size_t)blockIdx.x * blockDim.x + threadIdx.x) * 8;
  float am = absmax[i >> 6];
  int4 c0 = *reinterpret_cast<const int4*>(codes + i);
  int4 c1 = *reinterpret_cast<const int4*>(codes + i + 4);
  uint4 o;
  o.x = pack_h2(lut[c0.x] * am, lut[c0.y] * am);
  o.y = pack_h2(lut[c0.z] * am, lut[c0.w] * am);
  o.z = pack_h2(lut[c1.x] * am, lut[c1.y] * am);
  o.w = pack_h2(lut[c1.z] * am, lut[c1.w] * am);
  *reinterpret_cast<uint4*>(g_W + i) = o;
}

__global__ void k_conv_x(const float* __restrict__ x){
  size_t i = ((size_t)blockIdx.x * blockDim.x + threadIdx.x) * 8;
  float4 a = *reinterpret_cast<const float4*>(x + i);
  float4 b = *reinterpret_cast<const float4*>(x + i + 4);
  uint4 o;
  o.x = pack_h2(a.x, a.y);  o.y = pack_h2(a.z, a.w);
  o.z = pack_h2(b.x, b.y);  o.w = pack_h2(b.z, b.w);
  *reinterpret_cast<uint4*>(g_X + i) = o;
}

__global__ void k_dequant_b(const int* __restrict__ codes, const float* __restrict__ absmax){
  __shared__ float lut[16];
  if (threadIdx.x < 16) lut[threadIdx.x] = NF4_CB[threadIdx.x];
  __syncthreads();
  int i = blockIdx.x * blockDim.x + threadIdx.x;
  if (i < D_OUT) g_bias[i] = lut[codes[i]] * absmax[i >> 6];
}

// ======================= GEMM =======================
#define A_BYTES     (MT * KC * 2)            // 16 KB
#define STAGE_BYTES ((MT + NT) * KC * 2)     // 48 KB per chunk
#define HALF_BYTES  (2 * STAGE_BYTES)        // 96 KB per pair
#define SMEM_BYTES  (2 * HALF_BYTES)         // 192 KB -> 1 CTA/SM

// load one K-chunk (chunk index kt) into chunk-slot at `base`.
__device__ __forceinline__ void load_chunk(uint32_t base, int kt,
                                           const __half* gA, const __half* gB){
  int t = threadIdx.x;
  #pragma unroll
  for (int i = 0; i < 4; ++i){                 // A: 128 rows x 8 chunks = 1024
    int ci  = t + i * NTHREADS;
    int row = ci >> 3, c = ci & 7;
    uint32_t sw = (uint32_t)((c ^ (row & 7)) << 4);
    cp16(base + (uint32_t)(row * 128) + sw,
         gA + (size_t)row * D_IN + kt * KC + c * 8);
  }
  #pragma unroll
  for (int i = 0; i < 8; ++i){                 // B: 256 rows x 8 chunks = 2048
    int ci  = t + i * NTHREADS;
    int row = ci >> 3, c = ci & 7;
    uint32_t sw = (uint32_t)((c ^ (row & 7)) << 4);
    cp16(base + A_BYTES + (uint32_t)(row * 128) + sw,
         gB + (size_t)row * D_IN + kt * KC + c * 8);
  }
}

__global__ void __launch_bounds__(NTHREADS, 1)
k_gemm(float* __restrict__ out){
  extern __shared__ char smem[];
  uint32_t sb = smem_u32(smem);
  const int tid = threadIdx.x;
  const int wid = tid >> 5;
  const int l   = tid & 31;

  const int m0g = blockIdx.y * MT;
  const int n0g = blockIdx.x * NT;
  const __half* gA = g_X + (size_t)m0g * D_IN;
  const __half* gB = g_W + (size_t)n0g * D_IN;

  // warp layout: 2 (m) x 4 (n); warp tile 64(m) x 64(n)
  const int wm = (wid & 1) * 64;
  const int wn = (wid >> 1) * 64;

  // ldmatrix lane addressing
  const int rA   = wm + (l & 15);
  const int hiA  = l >> 4;
  const int r7A  = rA & 7;
  const int rB   = wn + ((l & 16) >> 1) + (l & 7);
  const int hiB  = (l >> 3) & 1;
  const int r7B  = rB & 7;

  float acc[4][8][4];
  #pragma unroll
  for (int f = 0; f < 4; ++f)
    #pragma unroll
    for (int j = 0; j < 8; ++j)
      #pragma unroll
      for (int q = 0; q < 4; ++q) acc[f][j][q] = 0.f;

  // prologue: pair 0 (chunks 0,1) into half 0
  load_chunk(sb, 0, gA, gB);
  load_chunk(sb + STAGE_BYTES, 1, gA, gB);
  cp_commit();

  for (int p = 0; p < KITERS / 2; ++p){
    cp_wait<0>();       // pair p resident
    __syncthreads();    // publish pair p; order compute(p-1) before overwrite

    if (p + 1 < KITERS / 2){
      uint32_t nb = sb + (uint32_t)(((p + 1) & 1) * HALF_BYTES);
      load_chunk(nb, 2 * p + 2, gA, gB);
      load_chunk(nb + STAGE_BYTES, 2 * p + 3, gA, gB);
      cp_commit();
    }

    uint32_t hb = sb + (uint32_t)((p & 1) * HALF_BYTES);
    #pragma unroll
    for (int half = 0; half < 2; ++half){     // two chunks in this pair
      uint32_t As = hb + (uint32_t)(half * STAGE_BYTES);
      uint32_t Bs = As + A_BYTES;
      uint32_t baseA = As + (uint32_t)(rA * 128);
      uint32_t baseB = Bs + (uint32_t)(rB * 128);

      #pragma unroll
      for (int ks = 0; ks < 4; ++ks){
        uint32_t csA = (uint32_t)(((2 * ks + hiA) ^ r7A) << 4);
        uint32_t csB = (uint32_t)(((2 * ks + hiB) ^ r7B) << 4);
        uint32_t a[4][4];
        #pragma unroll
        for (int f = 0; f < 4; ++f)
          ldsm_x4(a[f], baseA + (uint32_t)(f * 2048) + csA);
        #pragma unroll
        for (int nf = 0; nf < 4; ++nf){
          uint32_t b[4];
          ldsm_x4(b, baseB + (uint32_t)(nf * 2048) + csB);
          #pragma unroll
          for (int f = 0; f < 4; ++f){
            mma16816(acc[f][2 * nf + 0], a[f], b + 0);
            mma16816(acc[f][2 * nf + 1], a[f], b + 2);
          }
        }
      }
    }
  }

  // ---------------- epilogue ----------------
  const int gid = l >> 2, tig = l & 3;
  const int colbase = n0g + wn + 2 * tig;
  #pragma unroll
  for (int f = 0; f < 4; ++f){
    int row0 = m0g + wm + 16 * f + gid;
    float* o0 = out + (size_t)row0 * D_OUT;
    float* o1 = o0 + (size_t)8 * D_OUT;
    #pragma unroll
    for (int j = 0; j < 8; ++j){
      int cg = colbase + 8 * j;
      float b0 = g_bias[cg], b1 = g_bias[cg + 1];
      float2 v0 = { acc[f][j][0] + b0, acc[f][j][1] + b1 };
      float2 v1 = { acc[f][j][2] + b0, acc[f][j][3] + b1 };
      *reinterpret_cast<float2*>(o0 + cg) = v0;
      *reinterpret_cast<float2*>(o1 + cg) = v1;
    }
  }
}

// ======================= launch =======================
extern "C" void kernel_launch(void* const* d_in, const int* in_sizes, int n_in,
                              void* d_out, int out_size){
  const float* x  = (const float*)d_in[0];
  const int*   wc = (const int*)  d_in[1];
  const float* wa = (const float*)d_in[2];
  const int*   bc = (const int*)  d_in[3];
  const float* ba = (const float*)d_in[4];
  float* out = (float*)d_out;

  cudaFuncSetAttribute(k_gemm, cudaFuncAttributeMaxDynamicSharedMemorySize, SMEM_BYTES);

  k_dequant_w<<<(int)(((size_t)D_OUT * D_IN / 8) / 256), 256>>>(wc, wa);
  k_conv_x   <<<(int)(((size_t)M_TOT * D_IN / 8) / 256), 256>>>(x);
  k_dequant_b<<<(D_OUT + 255) / 256, 256>>>(bc, ba);

  dim3 grid(D_OUT / NT, M_TOT / MT);   // (16, 64)
  k_gemm<<<grid, NTHREADS, SMEM_BYTES>>>(out);
}

// round 9
// speedup vs baseline: 1.1161x; 1.0231x over previous
#include <cuda_runtime.h>
#include <cuda_fp16.h>
#include <cstdint>

// ======================= problem sizes =======================
#define D_IN   4096
#define D_OUT  4096
#define M_TOT  8192
#define MT     128             // CTA M tile
#define NT     128             // CTA N tile
#define KC     64              // K chunk: 64 fp16 = 128B rows (SW128)
#define STAGES 3
#define KITERS (D_IN / KC)     // 64
#define NTHREADS 128           // 4 warps, warp tile 64x64, 2 CTAs/SM

// ======================= scratch =======================
static __device__ __half g_W[(size_t)D_OUT * D_IN];   // 32 MB
static __device__ __half g_X[(size_t)M_TOT * D_IN];   // 64 MB
static __device__ float  g_bias[D_OUT];

__constant__ float NF4_CB[16] = {
  -1.0f, -0.6961928009986877f, -0.5250730514526367f, -0.39491748809814453f,
  -0.28444138169288635f, -0.18477343022823334f, -0.09105003625154495f, 0.0f,
  0.07958029955625534f, 0.16093020141124725f, 0.24611230194568634f,
  0.33791524171829224f, 0.44070982933044434f, 0.5626170039176941f,
  0.6848514676094055f, 1.0f };

// ======================= helpers =======================
__device__ __forceinline__ uint32_t smem_u32(const void* p){
  uint32_t a;
  asm("{ .reg .u64 t; cvta.to.shared.u64 t, %1; cvt.u32.u64 %0, t; }" : "=r"(a) : "l"(p));
  return a;
}
__device__ __forceinline__ uint32_t pack_h2(float a, float b){
  __half2 h = __floats2half2_rn(a, b);
  return *reinterpret_cast<uint32_t*>(&h);
}
__device__ __forceinline__ void cp16(uint32_t s, const void* g){
  asm volatile("cp.async.cg.shared.global [%0], [%1], 16;" :: "r"(s), "l"(g) : "memory");
}
__device__ __forceinline__ void cp_commit(){
  asm volatile("cp.async.commit_group;" ::: "memory");
}
template<int N> __device__ __forceinline__ void cp_wait(){
  asm volatile("cp.async.wait_group %0;" :: "n"(N) : "memory");
}
__device__ __forceinline__ void ldsm_x4(uint32_t* r, uint32_t addr){
  asm volatile("ldmatrix.sync.aligned.m8n8.x4.shared.b16 {%0,%1,%2,%3}, [%4];"
               : "=r"(r[0]), "=r"(r[1]), "=r"(r[2]), "=r"(r[3]) : "r"(addr));
}
__device__ __forceinline__ void mma16816(float* c, const uint32_t* a, const uint32_t* b){
  asm volatile("mma.sync.aligned.m16n8k16.row.col.f32.f16.f16.f32 "
               "{%0,%1,%2,%3}, {%4,%5,%6,%7}, {%8,%9}, {%0,%1,%2,%3};"
               : "+f"(c[0]), "+f"(c[1]), "+f"(c[2]), "+f"(c[3])
               : "r"(a[0]), "r"(a[1]), "r"(a[2]), "r"(a[3]), "r"(b[0]), "r"(b[1]));
}

// ======================= fused prep kernel =======================
// blocks [0, WBLK)            : dequant W  (8 elems/thread)
// blocks [WBLK, WBLK+XBLK)    : convert X  (8 elems/thread)
// blocks [WBLK+XBLK, +BBLK)   : dequant bias
#define WBLK ((int)(((size_t)D_OUT * D_IN / 8) / 256))   // 8192
#define XBLK ((int)(((size_t)M_TOT * D_IN / 8) / 256))   // 16384
#define BBLK (D_OUT / 256)                               // 16

__global__ void k_prep(const float* __restrict__ x,
                       const int* __restrict__ wc, const float* __restrict__ wa,
                       const int* __restrict__ bc, const float* __restrict__ ba){
  __shared__ float lut[16];
  if (threadIdx.x < 16) lut[threadIdx.x] = NF4_CB[threadIdx.x];
  __syncthreads();
  int b = blockIdx.x;
  if (b < WBLK){
    size_t i = ((size_t)b * 256 + threadIdx.x) * 8;
    float am = wa[i >> 6];
    int4 c0 = *reinterpret_cast<const int4*>(wc + i);
    int4 c1 = *reinterpret_cast<const int4*>(wc + i + 4);
    uint4 o;
    o.x = pack_h2(lut[c0.x] * am, lut[c0.y] * am);
    o.y = pack_h2(lut[c0.z] * am, lut[c0.w] * am);
    o.z = pack_h2(lut[c1.x] * am, lut[c1.y] * am);
    o.w = pack_h2(lut[c1.z] * am, lut[c1.w] * am);
    *reinterpret_cast<uint4*>(g_W + i) = o;
  } else if (b < WBLK + XBLK){
    size_t i = ((size_t)(b - WBLK) * 256 + threadIdx.x) * 8;
    float4 a = *reinterpret_cast<const float4*>(x + i);
    float4 c = *reinterpret_cast<const float4*>(x + i + 4);
    uint4 o;
    o.x = pack_h2(a.x, a.y);  o.y = pack_h2(a.z, a.w);
    o.z = pack_h2(c.x, c.y);  o.w = pack_h2(c.z, c.w);
    *reinterpret_cast<uint4*>(g_X + i) = o;
  } else {
    int i = (b - WBLK - XBLK) * 256 + threadIdx.x;
    if (i < D_OUT) g_bias[i] = lut[bc[i]] * ba[i >> 6];
  }
}

// ======================= GEMM =======================
#define A_BYTES     (MT * KC * 2)            // 16 KB
#define STAGE_BYTES ((MT + NT) * KC * 2)     // 32 KB
#define SMEM_BYTES  (STAGES * STAGE_BYTES)   // 96 KB -> 2 CTAs/SM

// load one K-chunk (chunk index kt) into stage s. 128 threads, 16 x 16B each.
__device__ __forceinline__ void load_stage(uint32_t sb, int s, int kt,
                                           const __half* gA, const __half* gB){
  uint32_t base = sb + (uint32_t)s * STAGE_BYTES;
  int t = threadIdx.x;
  #pragma unroll
  for (int i = 0; i < 8; ++i){                 // A: 128 rows x 8 chunks = 1024
    int ci  = t + i * NTHREADS;
    int row = ci >> 3, c = ci & 7;
    uint32_t sw = (uint32_t)((c ^ (row & 7)) << 4);
    cp16(base + (uint32_t)(row * 128) + sw,
         gA + (size_t)row * D_IN + kt * KC + c * 8);
  }
  #pragma unroll
  for (int i = 0; i < 8; ++i){                 // B: 128 rows x 8 chunks = 1024
    int ci  = t + i * NTHREADS;
    int row = ci >> 3, c = ci & 7;
    uint32_t sw = (uint32_t)((c ^ (row & 7)) << 4);
    cp16(base + A_BYTES + (uint32_t)(row * 128) + sw,
         gB + (size_t)row * D_IN + kt * KC + c * 8);
  }
}

__global__ void __launch_bounds__(NTHREADS, 2)
k_gemm(float* __restrict__ out){
  extern __shared__ char smem[];
  uint32_t sb = smem_u32(smem);
  const int tid = threadIdx.x;
  const int wid = tid >> 5;
  const int l   = tid & 31;

  const int m0g = blockIdx.y * MT;
  const int n0g = blockIdx.x * NT;
  const __half* gA = g_X + (size_t)m0g * D_IN;
  const __half* gB = g_W + (size_t)n0g * D_IN;

  // warp layout: 2 (m) x 2 (n); warp tile 64(m) x 64(n)
  const int wm = (wid & 1) * 64;
  const int wn = (wid >> 1) * 64;

  // ldmatrix lane addressing
  const int rA   = wm + (l & 15);
  const int hiA  = l >> 4;
  const int r7A  = rA & 7;
  const int rB   = wn + ((l & 16) >> 1) + (l & 7);
  const int hiB  = (l >> 3) & 1;
  const int r7B  = rB & 7;

  float acc[4][8][4];
  #pragma unroll
  for (int f = 0; f < 4; ++f)
    #pragma unroll
    for (int j = 0; j < 8; ++j)
      #pragma unroll
      for (int q = 0; q < 4; ++q) acc[f][j][q] = 0.f;

  // prologue: stages 0..STAGES-2
  #pragma unroll
  for (int s = 0; s < STAGES - 1; ++s){
    load_stage(sb, s, s, gA, gB);
    cp_commit();
  }

  for (int kt = 0; kt < KITERS; ++kt){
    cp_wait<STAGES - 2>();
    __syncthreads();   // publish stage kt; order compute(kt-1) before overwrite

    int kn = kt + STAGES - 1;
    if (kn < KITERS) load_stage(sb, kn % STAGES, kn, gA, gB);
    cp_commit();

    uint32_t As = sb + (uint32_t)((kt % STAGES) * STAGE_BYTES);
    uint32_t Bs = As + A_BYTES;
    uint32_t baseA = As + (uint32_t)(rA * 128);
    uint32_t baseB = Bs + (uint32_t)(rB * 128);

    #pragma unroll
    for (int ks = 0; ks < 4; ++ks){
      uint32_t csA = (uint32_t)(((2 * ks + hiA) ^ r7A) << 4);
      uint32_t csB = (uint32_t)(((2 * ks + hiB) ^ r7B) << 4);
      uint32_t a[4][4];
      #pragma unroll
      for (int f = 0; f < 4; ++f)
        ldsm_x4(a[f], baseA + (uint32_t)(f * 2048) + csA);
      #pragma unroll
      for (int nf = 0; nf < 4; ++nf){
        uint32_t b[4];
        ldsm_x4(b, baseB + (uint32_t)(nf * 2048) + csB);
        #pragma unroll
        for (int f = 0; f < 4; ++f){
          mma16816(acc[f][2 * nf + 0], a[f], b + 0);
          mma16816(acc[f][2 * nf + 1], a[f], b + 2);
        }
      }
    }
  }

  // ---------------- epilogue ----------------
  const int gid = l >> 2, tig = l & 3;
  const int colbase = n0g + wn + 2 * tig;
  #pragma unroll
  for (int f = 0; f < 4; ++f){
    int row0 = m0g + wm + 16 * f + gid;
    float* o0 = out + (size_t)row0 * D_OUT;
    float* o1 = o0 + (size_t)8 * D_OUT;
    #pragma unroll
    for (int j = 0; j < 8; ++j){
      int cg = colbase + 8 * j;
      float b0 = g_bias[cg], b1 = g_bias[cg + 1];
      float2 v0 = { acc[f][j][0] + b0, acc[f][j][1] + b1 };
      float2 v1 = { acc[f][j][2] + b0, acc[f][j][3] + b1 };
      *reinterpret_cast<float2*>(o0 + cg) = v0;
      *reinterpret_cast<float2*>(o1 + cg) = v1;
    }
  }
}

// ======================= launch =======================
extern "C" void kernel_launch(void* const* d_in, const int* in_sizes, int n_in,
                              void* d_out, int out_size){
  const float* x  = (const float*)d_in[0];
  const int*   wc = (const int*)  d_in[1];
  const float* wa = (const float*)d_in[2];
  const int*   bc = (const int*)  d_in[3];
  const float* ba = (const float*)d_in[4];
  float* out = (float*)d_out;

  cudaFuncSetAttribute(k_gemm, cudaFuncAttributeMaxDynamicSharedMemorySize, SMEM_BYTES);

  k_prep<<<WBLK + XBLK + BBLK, 256>>>(x, wc, wa, bc, ba);

  dim3 grid(D_OUT / NT, M_TOT / MT);   // (32, 64)
  k_gemm<<<grid, NTHREADS, SMEM_BYTES>>>(out);
}

// round 10
// speedup vs baseline: 1.1988x; 1.0740x over previous
#include <cuda_runtime.h>
#include <cuda_fp16.h>
#include <cstdint>

// ======================= problem sizes =======================
#define D_IN   4096
#define D_OUT  4096
#define M_TOT  8192
#define MT     128             // CTA M tile
#define NT     128             // CTA N tile
#define KC     64              // K chunk: 64 fp16 = 128B rows (SW128)
#define STAGES 3
#define KITERS (D_IN / KC)     // 64
#define NTHREADS 128           // 4 warps, warp tile 64x64, 2 CTAs/SM

// ======================= scratch =======================
static __device__ __half g_W[(size_t)D_OUT * D_IN];   // 32 MB
static __device__ __half g_X[(size_t)M_TOT * D_IN];   // 64 MB
static __device__ float  g_bias[D_OUT];

__constant__ float NF4_CB[16] = {
  -1.0f, -0.6961928009986877f, -0.5250730514526367f, -0.39491748809814453f,
  -0.28444138169288635f, -0.18477343022823334f, -0.09105003625154495f, 0.0f,
  0.07958029955625534f, 0.16093020141124725f, 0.24611230194568634f,
  0.33791524171829224f, 0.44070982933044434f, 0.5626170039176941f,
  0.6848514676094055f, 1.0f };

// ======================= helpers =======================
__device__ __forceinline__ uint32_t smem_u32(const void* p){
  uint32_t a;
  asm("{ .reg .u64 t; cvta.to.shared.u64 t, %1; cvt.u32.u64 %0, t; }" : "=r"(a) : "l"(p));
  return a;
}
__device__ __forceinline__ uint32_t pack_h2(float a, float b){
  __half2 h = __floats2half2_rn(a, b);
  return *reinterpret_cast<uint32_t*>(&h);
}
__device__ __forceinline__ void cp16(uint32_t s, const void* g){
  asm volatile("cp.async.cg.shared.global [%0], [%1], 16;" :: "r"(s), "l"(g) : "memory");
}
__device__ __forceinline__ void ldsm_x4(uint32_t* r, uint32_t addr){
  asm volatile("ldmatrix.sync.aligned.m8n8.x4.shared.b16 {%0,%1,%2,%3}, [%4];"
               : "=r"(r[0]), "=r"(r[1]), "=r"(r[2]), "=r"(r[3]) : "r"(addr));
}
__device__ __forceinline__ void mma16816(float* c, const uint32_t* a, const uint32_t* b){
  asm volatile("mma.sync.aligned.m16n8k16.row.col.f32.f16.f16.f32 "
               "{%0,%1,%2,%3}, {%4,%5,%6,%7}, {%8,%9}, {%0,%1,%2,%3};"
               : "+f"(c[0]), "+f"(c[1]), "+f"(c[2]), "+f"(c[3])
               : "r"(a[0]), "r"(a[1]), "r"(a[2]), "r"(a[3]), "r"(b[0]), "r"(b[1]));
}

#define MBAR_INIT(addr, cnt) \
  asm volatile("mbarrier.init.shared.b64 [%0], %1;" :: "r"(addr), "r"(cnt) : "memory")

#define MBAR_ARRIVE(addr) \
  asm volatile("mbarrier.arrive.shared.b64 _, [%0];" :: "r"(addr) : "memory")

#define MBAR_WAIT(addr, ph) do {                                               \
  uint32_t _m = (addr), _p = (ph), _d;                                         \
  asm volatile("{\n\t.reg .pred p;\n\t"                                        \
    "mbarrier.try_wait.parity.acquire.cta.shared::cta.b64 p, [%1], %2;\n\t"    \
    "selp.b32 %0, 1, 0, p;\n\t}"                                               \
    : "=r"(_d) : "r"(_m), "r"(_p) : "memory");                                 \
  if (!_d) {                                                                   \
    asm volatile("{\n\t.reg .pred P1;\n"                                       \
      "WL%=:\n\t"                                                              \
      "mbarrier.try_wait.parity.acquire.cta.shared::cta.b64 P1, [%0], %1, 0x989680;\n\t" \
      "@P1 bra.uni WD%=;\n\t"                                                  \
      "bra.uni WL%=;\n"                                                        \
      "WD%=:\n\t}" :: "r"(_m), "r"(_p) : "memory");                            \
  }                                                                            \
} while (0)

// ======================= fused prep kernel =======================
#define WBLK ((int)(((size_t)D_OUT * D_IN / 8) / 256))   // 8192
#define XBLK ((int)(((size_t)M_TOT * D_IN / 8) / 256))   // 16384
#define BBLK (D_OUT / 256)                               // 16

__global__ void k_prep(const float* __restrict__ x,
                       const int* __restrict__ wc, const float* __restrict__ wa,
                       const int* __restrict__ bc, const float* __restrict__ ba){
  __shared__ float lut[16];
  if (threadIdx.x < 16) lut[threadIdx.x] = NF4_CB[threadIdx.x];
  __syncthreads();
  int b = blockIdx.x;
  if (b < WBLK){
    size_t i = ((size_t)b * 256 + threadIdx.x) * 8;
    float am = wa[i >> 6];
    int4 c0 = *reinterpret_cast<const int4*>(wc + i);
    int4 c1 = *reinterpret_cast<const int4*>(wc + i + 4);
    uint4 o;
    o.x = pack_h2(lut[c0.x] * am, lut[c0.y] * am);
    o.y = pack_h2(lut[c0.z] * am, lut[c0.w] * am);
    o.z = pack_h2(lut[c1.x] * am, lut[c1.y] * am);
    o.w = pack_h2(lut[c1.z] * am, lut[c1.w] * am);
    *reinterpret_cast<uint4*>(g_W + i) = o;
  } else if (b < WBLK + XBLK){
    size_t i = ((size_t)(b - WBLK) * 256 + threadIdx.x) * 8;
    float4 a = *reinterpret_cast<const float4*>(x + i);
    float4 c = *reinterpret_cast<const float4*>(x + i + 4);
    uint4 o;
    o.x = pack_h2(a.x, a.y);  o.y = pack_h2(a.z, a.w);
    o.z = pack_h2(c.x, c.y);  o.w = pack_h2(c.z, c.w);
    *reinterpret_cast<uint4*>(g_X + i) = o;
  } else {
    int i = (b - WBLK - XBLK) * 256 + threadIdx.x;
    if (i < D_OUT) g_bias[i] = lut[bc[i]] * ba[i >> 6];
  }
}

// ======================= GEMM =======================
// SMEM: [0..) mbarriers (full[3] then empty[3]); data stages at 1024.
#define SOFF_FULL   0
#define SOFF_EMPTY  (SOFF_FULL + STAGES * 8)
#define SOFF_DATA   1024
#define A_BYTES     (MT * KC * 2)            // 16 KB
#define STAGE_BYTES ((MT + NT) * KC * 2)     // 32 KB
#define SMEM_BYTES  (SOFF_DATA + STAGES * STAGE_BYTES)   // 99328 -> 2 CTAs/SM

// issue the 16 cp.async for one K-chunk into stage base
__device__ __forceinline__ void load_stage(uint32_t base, int kt,
                                           const __half* gA, const __half* gB){
  int t = threadIdx.x;
  #pragma unroll
  for (int i = 0; i < 8; ++i){                 // A: 128 rows x 8 chunks
    int ci  = t + i * NTHREADS;
    int row = ci >> 3, c = ci & 7;
    uint32_t sw = (uint32_t)((c ^ (row & 7)) << 4);
    cp16(base + (uint32_t)(row * 128) + sw,
         gA + (size_t)row * D_IN + kt * KC + c * 8);
  }
  #pragma unroll
  for (int i = 0; i < 8; ++i){                 // B: 128 rows x 8 chunks
    int ci  = t + i * NTHREADS;
    int row = ci >> 3, c = ci & 7;
    uint32_t sw = (uint32_t)((c ^ (row & 7)) << 4);
    cp16(base + A_BYTES + (uint32_t)(row * 128) + sw,
         gB + (size_t)row * D_IN + kt * KC + c * 8);
  }
}

__global__ void __launch_bounds__(NTHREADS, 2)
k_gemm(float* __restrict__ out){
  extern __shared__ char smem[];
  uint32_t sb = smem_u32(smem);
  const int tid = threadIdx.x;
  const int wid = tid >> 5;
  const int l   = tid & 31;

  if (tid == 0){
    #pragma unroll
    for (int s = 0; s < STAGES; ++s){
      MBAR_INIT(sb + SOFF_FULL  + s * 8, NTHREADS);  // 128 cp-arrives
      MBAR_INIT(sb + SOFF_EMPTY + s * 8, 4);         // 1 arrive per warp
    }
  }
  __syncthreads();   // only block-wide barrier in the kernel

  const int m0g = blockIdx.y * MT;
  const int n0g = blockIdx.x * NT;
  const __half* gA = g_X + (size_t)m0g * D_IN;
  const __half* gB = g_W + (size_t)n0g * D_IN;

  // warp layout: 2 (m) x 2 (n); warp tile 64(m) x 64(n)
  const int wm = (wid & 1) * 64;
  const int wn = (wid >> 1) * 64;

  // ldmatrix lane addressing
  const int rA   = wm + (l & 15);
  const int hiA  = l >> 4;
  const int r7A  = rA & 7;
  const int rB   = wn + ((l & 16) >> 1) + (l & 7);
  const int hiB  = (l >> 3) & 1;
  const int r7B  = rB & 7;

  float acc[4][8][4];
  #pragma unroll
  for (int f = 0; f < 4; ++f)
    #pragma unroll
    for (int j = 0; j < 8; ++j)
      #pragma unroll
      for (int q = 0; q < 4; ++q) acc[f][j][q] = 0.f;

  // cursors: producer starts phase 1 (fresh-barrier trick: first STAGES
  // empty-waits pass immediately); consumer starts phase 0.
  int ps = 0, pp = 1;
  int cs = 0, cp = 0;

  // prologue: fill stages 0..STAGES-2
  #pragma unroll
  for (int s = 0; s < STAGES - 1; ++s){
    MBAR_WAIT(sb + SOFF_EMPTY + ps * 8, pp);
    load_stage(sb + SOFF_DATA + (uint32_t)ps * STAGE_BYTES, s, gA, gB);
    asm volatile("cp.async.mbarrier.arrive.noinc.shared::cta.b64 [%0];"
                 :: "r"(sb + SOFF_FULL + ps * 8) : "memory");
    if (++ps == STAGES){ ps = 0; pp ^= 1; }
  }

  for (int kt = 0; kt < KITERS; ++kt){
    // produce chunk kt + STAGES - 1
    int kp = kt + STAGES - 1;
    if (kp < KITERS){
      MBAR_WAIT(sb + SOFF_EMPTY + ps * 8, pp);
      load_stage(sb + SOFF_DATA + (uint32_t)ps * STAGE_BYTES, kp, gA, gB);
      asm volatile("cp.async.mbarrier.arrive.noinc.shared::cta.b64 [%0];"
                   :: "r"(sb + SOFF_FULL + ps * 8) : "memory");
      if (++ps == STAGES){ ps = 0; pp ^= 1; }
    }

    // consume chunk kt
    MBAR_WAIT(sb + SOFF_FULL + cs * 8, cp);
    uint32_t As = sb + SOFF_DATA + (uint32_t)cs * STAGE_BYTES;
    uint32_t Bs = As + A_BYTES;
    uint32_t baseA = As + (uint32_t)(rA * 128);
    uint32_t baseB = Bs + (uint32_t)(rB * 128);

    #pragma unroll
    for (int ks = 0; ks < 4; ++ks){
      uint32_t csA = (uint32_t)(((2 * ks + hiA) ^ r7A) << 4);
      uint32_t csB = (uint32_t)(((2 * ks + hiB) ^ r7B) << 4);
      uint32_t a[4][4];
      #pragma unroll
      for (int f = 0; f < 4; ++f)
        ldsm_x4(a[f], baseA + (uint32_t)(f * 2048) + csA);
      #pragma unroll
      for (int nf = 0; nf < 4; ++nf){
        uint32_t b[4];
        ldsm_x4(b, baseB + (uint32_t)(nf * 2048) + csB);
        #pragma unroll
        for (int f = 0; f < 4; ++f){
          mma16816(acc[f][2 * nf + 0], a[f], b + 0);
          mma16816(acc[f][2 * nf + 1], a[f], b + 2);
        }
      }
    }

    __syncwarp();
    if (l == 0) MBAR_ARRIVE(sb + SOFF_EMPTY + cs * 8);
    if (++cs == STAGES){ cs = 0; cp ^= 1; }
  }

  // ---------------- epilogue ----------------
  const int gid = l >> 2, tig = l & 3;
  const int colbase = n0g + wn + 2 * tig;
  #pragma unroll
  for (int f = 0; f < 4; ++f){
    int row0 = m0g + wm + 16 * f + gid;
    float* o0 = out + (size_t)row0 * D_OUT;
    float* o1 = o0 + (size_t)8 * D_OUT;
    #pragma unroll
    for (int j = 0; j < 8; ++j){
      int cg = colbase + 8 * j;
      float b0 = g_bias[cg], b1 = g_bias[cg + 1];
      float2 v0 = { acc[f][j][0] + b0, acc[f][j][1] + b1 };
      float2 v1 = { acc[f][j][2] + b0, acc[f][j][3] + b1 };
      *reinterpret_cast<float2*>(o0 + cg) = v0;
      *reinterpret_cast<float2*>(o1 + cg) = v1;
    }
  }
}

// ======================= launch =======================
extern "C" void kernel_launch(void* const* d_in, const int* in_sizes, int n_in,
                              void* d_out, int out_size){
  const float* x  = (const float*)d_in[0];
  const int*   wc = (const int*)  d_in[1];
  const float* wa = (const float*)d_in[2];
  const int*   bc = (const int*)  d_in[3];
  const float* ba = (const float*)d_in[4];
  float* out = (float*)d_out;

  cudaFuncSetAttribute(k_gemm, cudaFuncAttributeMaxDynamicSharedMemorySize, SMEM_BYTES);

  k_prep<<<WBLK + XBLK + BBLK, 256>>>(x, wc, wa, bc, ba);

  dim3 grid(D_OUT / NT, M_TOT / MT);   // (32, 64)
  k_gemm<<<grid, NTHREADS, SMEM_BYTES>>>(out);
}

// round 11
// speedup vs baseline: 1.1992x; 1.0004x over previous
#include <cuda_runtime.h>
#include <cuda_fp16.h>
#include <cstdint>

// ======================= problem sizes =======================
#define D_IN   4096
#define D_OUT  4096
#define M_TOT  8192
#define MT     128             // CTA M tile
#define NT     128             // CTA N tile
#define KC     64              // K chunk: 64 fp16 = 128B rows (SW128)
#define STAGES 3
#define KITERS (D_IN / KC)     // 64
#define NTHREADS 128           // 4 warps, warp tile 64x64, 2 CTAs/SM

// ======================= scratch =======================
static __device__ __half g_W[(size_t)D_OUT * D_IN];   // 32 MB
static __device__ __half g_X[(size_t)M_TOT * D_IN];   // 64 MB
static __device__ float  g_bias[D_OUT];

__constant__ float NF4_CB[16] = {
  -1.0f, -0.6961928009986877f, -0.5250730514526367f, -0.39491748809814453f,
  -0.28444138169288635f, -0.18477343022823334f, -0.09105003625154495f, 0.0f,
  0.07958029955625534f, 0.16093020141124725f, 0.24611230194568634f,
  0.33791524171829224f, 0.44070982933044434f, 0.5626170039176941f,
  0.6848514676094055f, 1.0f };

// ======================= helpers =======================
__device__ __forceinline__ uint32_t smem_u32(const void* p){
  uint32_t a;
  asm("{ .reg .u64 t; cvta.to.shared.u64 t, %1; cvt.u32.u64 %0, t; }" : "=r"(a) : "l"(p));
  return a;
}
__device__ __forceinline__ uint32_t pack_h2(float a, float b){
  __half2 h = __floats2half2_rn(a, b);
  return *reinterpret_cast<uint32_t*>(&h);
}
__device__ __forceinline__ void cp16(uint32_t s, const void* g){
  asm volatile("cp.async.cg.shared.global [%0], [%1], 16;" :: "r"(s), "l"(g) : "memory");
}
__device__ __forceinline__ void ldsm_x4(uint32_t* r, uint32_t addr){
  asm volatile("ldmatrix.sync.aligned.m8n8.x4.shared.b16 {%0,%1,%2,%3}, [%4];"
               : "=r"(r[0]), "=r"(r[1]), "=r"(r[2]), "=r"(r[3]) : "r"(addr));
}
__device__ __forceinline__ void mma16816(float* c, const uint32_t* a, const uint32_t* b){
  asm volatile("mma.sync.aligned.m16n8k16.row.col.f32.f16.f16.f32 "
               "{%0,%1,%2,%3}, {%4,%5,%6,%7}, {%8,%9}, {%0,%1,%2,%3};"
               : "+f"(c[0]), "+f"(c[1]), "+f"(c[2]), "+f"(c[3])
               : "r"(a[0]), "r"(a[1]), "r"(a[2]), "r"(a[3]), "r"(b[0]), "r"(b[1]));
}

#define MBAR_INIT(addr, cnt) \
  asm volatile("mbarrier.init.shared.b64 [%0], %1;" :: "r"(addr), "r"(cnt) : "memory")

#define MBAR_ARRIVE(addr) \
  asm volatile("mbarrier.arrive.shared.b64 _, [%0];" :: "r"(addr) : "memory")

#define MBAR_WAIT(addr, ph) do {                                               \
  uint32_t _m = (addr), _p = (ph), _d;                                         \
  asm volatile("{\n\t.reg .pred p;\n\t"                                        \
    "mbarrier.try_wait.parity.acquire.cta.shared::cta.b64 p, [%1], %2;\n\t"    \
    "selp.b32 %0, 1, 0, p;\n\t}"                                               \
    : "=r"(_d) : "r"(_m), "r"(_p) : "memory");                                 \
  if (!_d) {                                                                   \
    asm volatile("{\n\t.reg .pred P1;\n"                                       \
      "WL%=:\n\t"                                                              \
      "mbarrier.try_wait.parity.acquire.cta.shared::cta.b64 P1, [%0], %1, 0x989680;\n\t" \
      "@P1 bra.uni WD%=;\n\t"                                                  \
      "bra.uni WL%=;\n"                                                        \
      "WD%=:\n\t}" :: "r"(_m), "r"(_p) : "memory");                            \
  }                                                                            \
} while (0)

// ======================= fused prep kernel =======================
#define WBLK ((int)(((size_t)D_OUT * D_IN / 8) / 256))   // 8192
#define XBLK ((int)(((size_t)M_TOT * D_IN / 8) / 256))   // 16384
#define BBLK (D_OUT / 256)                               // 16

__global__ void k_prep(const float* __restrict__ x,
                       const int* __restrict__ wc, const float* __restrict__ wa,
                       const int* __restrict__ bc, const float* __restrict__ ba){
  __shared__ float lut[16];
  if (threadIdx.x < 16) lut[threadIdx.x] = NF4_CB[threadIdx.x];
  __syncthreads();
  int b = blockIdx.x;
  if (b < WBLK){
    size_t i = ((size_t)b * 256 + threadIdx.x) * 8;
    float am = wa[i >> 6];
    int4 c0 = *reinterpret_cast<const int4*>(wc + i);
    int4 c1 = *reinterpret_cast<const int4*>(wc + i + 4);
    uint4 o;
    o.x = pack_h2(lut[c0.x] * am, lut[c0.y] * am);
    o.y = pack_h2(lut[c0.z] * am, lut[c0.w] * am);
    o.z = pack_h2(lut[c1.x] * am, lut[c1.y] * am);
    o.w = pack_h2(lut[c1.z] * am, lut[c1.w] * am);
    *reinterpret_cast<uint4*>(g_W + i) = o;
  } else if (b < WBLK + XBLK){
    size_t i = ((size_t)(b - WBLK) * 256 + threadIdx.x) * 8;
    float4 a = *reinterpret_cast<const float4*>(x + i);
    float4 c = *reinterpret_cast<const float4*>(x + i + 4);
    uint4 o;
    o.x = pack_h2(a.x, a.y);  o.y = pack_h2(a.z, a.w);
    o.z = pack_h2(c.x, c.y);  o.w = pack_h2(c.z, c.w);
    *reinterpret_cast<uint4*>(g_X + i) = o;
  } else {
    int i = (b - WBLK - XBLK) * 256 + threadIdx.x;
    if (i < D_OUT) g_bias[i] = lut[bc[i]] * ba[i >> 6];
  }
}

// ======================= GEMM =======================
#define SOFF_FULL   0
#define SOFF_EMPTY  (SOFF_FULL + STAGES * 8)
#define SOFF_DATA   1024
#define A_BYTES     (MT * KC * 2)            // 16 KB
#define STAGE_BYTES ((MT + NT) * KC * 2)     // 32 KB
#define SMEM_BYTES  (SOFF_DATA + STAGES * STAGE_BYTES)   // 99328 -> 2 CTAs/SM

__device__ __forceinline__ void load_stage(uint32_t base, int kt,
                                           const __half* gA, const __half* gB){
  int t = threadIdx.x;
  #pragma unroll
  for (int i = 0; i < 8; ++i){                 // A: 128 rows x 8 chunks
    int ci  = t + i * NTHREADS;
    int row = ci >> 3, c = ci & 7;
    uint32_t sw = (uint32_t)((c ^ (row & 7)) << 4);
    cp16(base + (uint32_t)(row * 128) + sw,
         gA + (size_t)row * D_IN + kt * KC + c * 8);
  }
  #pragma unroll
  for (int i = 0; i < 8; ++i){                 // B: 128 rows x 8 chunks
    int ci  = t + i * NTHREADS;
    int row = ci >> 3, c = ci & 7;
    uint32_t sw = (uint32_t)((c ^ (row & 7)) << 4);
    cp16(base + A_BYTES + (uint32_t)(row * 128) + sw,
         gB + (size_t)row * D_IN + kt * KC + c * 8);
  }
}

__global__ void __launch_bounds__(NTHREADS, 2)
k_gemm(float* __restrict__ out){
  extern __shared__ char smem[];
  uint32_t sb = smem_u32(smem);
  const int tid = threadIdx.x;
  const int wid = tid >> 5;
  const int l   = tid & 31;

  if (tid == 0){
    #pragma unroll
    for (int s = 0; s < STAGES; ++s){
      MBAR_INIT(sb + SOFF_FULL  + s * 8, NTHREADS);  // 128 cp-arrives
      MBAR_INIT(sb + SOFF_EMPTY + s * 8, 4);         // 1 arrive per warp
    }
  }
  __syncthreads();   // only block-wide barrier in the kernel

  const int m0g = blockIdx.y * MT;
  const int n0g = blockIdx.x * NT;
  const __half* gA = g_X + (size_t)m0g * D_IN;
  const __half* gB = g_W + (size_t)n0g * D_IN;

  // warp layout: 2 (m) x 2 (n); warp tile 64(m) x 64(n)
  const int wm = (wid & 1) * 64;
  const int wn = (wid >> 1) * 64;

  // ldmatrix lane addressing
  const int rA   = wm + (l & 15);
  const int hiA  = l >> 4;
  const int r7A  = rA & 7;
  const int rB   = wn + ((l & 16) >> 1) + (l & 7);
  const int hiB  = (l >> 3) & 1;
  const int r7B  = rB & 7;

  float acc[4][8][4];
  #pragma unroll
  for (int f = 0; f < 4; ++f)
    #pragma unroll
    for (int j = 0; j < 8; ++j)
      #pragma unroll
      for (int q = 0; q < 4; ++q) acc[f][j][q] = 0.f;

  // cursors: producer phase starts 1 (fresh-barrier parity trick)
  int ps = 0, pp = 1;
  int cs = 0, cp = 0;

  // prologue: fill stages 0..STAGES-2
  #pragma unroll
  for (int s = 0; s < STAGES - 1; ++s){
    MBAR_WAIT(sb + SOFF_EMPTY + ps * 8, pp);
    load_stage(sb + SOFF_DATA + (uint32_t)ps * STAGE_BYTES, s, gA, gB);
    asm volatile("cp.async.mbarrier.arrive.noinc.shared::cta.b64 [%0];"
                 :: "r"(sb + SOFF_FULL + ps * 8) : "memory");
    if (++ps == STAGES){ ps = 0; pp ^= 1; }
  }

  for (int kt = 0; kt < KITERS; ++kt){
    // produce chunk kt + STAGES - 1
    int kp = kt + STAGES - 1;
    if (kp < KITERS){
      MBAR_WAIT(sb + SOFF_EMPTY + ps * 8, pp);
      load_stage(sb + SOFF_DATA + (uint32_t)ps * STAGE_BYTES, kp, gA, gB);
      asm volatile("cp.async.mbarrier.arrive.noinc.shared::cta.b64 [%0];"
                   :: "r"(sb + SOFF_FULL + ps * 8) : "memory");
      if (++ps == STAGES){ ps = 0; pp ^= 1; }
    }

    // consume chunk kt
    MBAR_WAIT(sb + SOFF_FULL + cs * 8, cp);
    uint32_t As = sb + SOFF_DATA + (uint32_t)cs * STAGE_BYTES;
    uint32_t Bs = As + A_BYTES;
    uint32_t baseA = As + (uint32_t)(rA * 128);
    uint32_t baseB = Bs + (uint32_t)(rB * 128);

    #pragma unroll
    for (int ks = 0; ks < 4; ++ks){
      uint32_t csA = (uint32_t)(((2 * ks + hiA) ^ r7A) << 4);
      uint32_t csB = (uint32_t)(((2 * ks + hiB) ^ r7B) << 4);
      // batch ALL smem loads for this ks: 8 ldsm pipeline together, so only
      // the last one's latency is exposed (once per ks, not once per nf).
      uint32_t a[4][4], b[4][4];
      #pragma unroll
      for (int f = 0; f < 4; ++f)
        ldsm_x4(a[f], baseA + (uint32_t)(f * 2048) + csA);
      #pragma unroll
      for (int nf = 0; nf < 4; ++nf)
        ldsm_x4(b[nf], baseB + (uint32_t)(nf * 2048) + csB);
      // 32 MMAs with no smem dependencies
      #pragma unroll
      for (int nf = 0; nf < 4; ++nf)
        #pragma unroll
        for (int f = 0; f < 4; ++f){
          mma16816(acc[f][2 * nf + 0], a[f], b[nf] + 0);
          mma16816(acc[f][2 * nf + 1], a[f], b[nf] + 2);
        }
    }

    __syncwarp();
    if (l == 0) MBAR_ARRIVE(sb + SOFF_EMPTY + cs * 8);
    if (++cs == STAGES){ cs = 0; cp ^= 1; }
  }

  // ---------------- epilogue ----------------
  const int gid = l >> 2, tig = l & 3;
  const int colbase = n0g + wn + 2 * tig;
  #pragma unroll
  for (int f = 0; f < 4; ++f){
    int row0 = m0g + wm + 16 * f + gid;
    float* o0 = out + (size_t)row0 * D_OUT;
    float* o1 = o0 + (size_t)8 * D_OUT;
    #pragma unroll
    for (int j = 0; j < 8; ++j){
      int cg = colbase + 8 * j;
      float b0 = g_bias[cg], b1 = g_bias[cg + 1];
      float2 v0 = { acc[f][j][0] + b0, acc[f][j][1] + b1 };
      float2 v1 = { acc[f][j][2] + b0, acc[f][j][3] + b1 };
      *reinterpret_cast<float2*>(o0 + cg) = v0;
      *reinterpret_cast<float2*>(o1 + cg) = v1;
    }
  }
}

// ======================= launch =======================
extern "C" void kernel_launch(void* const* d_in, const int* in_sizes, int n_in,
                              void* d_out, int out_size){
  const float* x  = (const float*)d_in[0];
  const int*   wc = (const int*)  d_in[1];
  const float* wa = (const float*)d_in[2];
  const int*   bc = (const int*)  d_in[3];
  const float* ba = (const float*)d_in[4];
  float* out = (float*)d_out;

  cudaFuncSetAttribute(k_gemm, cudaFuncAttributeMaxDynamicSharedMemorySize, SMEM_BYTES);

  k_prep<<<WBLK + XBLK + BBLK, 256>>>(x, wc, wa, bc, ba);

  dim3 grid(D_OUT / NT, M_TOT / MT);   // (32, 64)
  k_gemm<<<grid, NTHREADS, SMEM_BYTES>>>(out);
}